// round 2
// baseline (speedup 1.0000x reference)
#include <cuda_runtime.h>
#include <cuda_bf16.h>
#include <math.h>
#include <stdint.h>

// ---------------- scratch (static device arrays; no allocation) ----------------
__device__ float g_qkv[16384 * 1536];      // QKV projection output
__device__ float g_scores[64 * 512 * 512]; // attention scores / probs
__device__ float g_attn[16384 * 512];      // attention output (pre out-proj)
__device__ float g_dec[16384 * 512];       // decoder features after ReLU
__device__ float g_em[16384 * 24];         // CRF emissions
__device__ float g_llh[32];                // per-batch (num - den)

// ---------------- generic fp32 SGEMM: C = act(alpha * A @ op(B) + bias) --------
// A: MxK row-major (lda). op(B): TRANSB ? B is NxK (B[n][k]) : B is KxN (B[k][n]).
// Batched via z: ptr += (z/zdiv)*outer + (z%zdiv)*inner.
#define BM 128
#define BN 128
#define BK 16
#define TM 8
#define TN 8

__global__ __launch_bounds__(256) void sgemm_kernel(
    const float* __restrict__ A, int lda, long long aOuter, long long aInner,
    const float* __restrict__ B, int ldb, long long bOuter, long long bInner,
    float* __restrict__ C, int ldc, long long cOuter, long long cInner,
    const float* __restrict__ bias,
    int M, int N, int K, float alpha, int flags, int zdiv)
{
    int z = blockIdx.z;
    A += (long long)(z / zdiv) * aOuter + (long long)(z % zdiv) * aInner;
    B += (long long)(z / zdiv) * bOuter + (long long)(z % zdiv) * bInner;
    C += (long long)(z / zdiv) * cOuter + (long long)(z % zdiv) * cInner;

    __shared__ float As[BK][BM + 4];
    __shared__ float Bs[BK][BN + 4];

    int tid = threadIdx.x;
    int tx = tid % 16, ty = tid / 16;
    int bm = blockIdx.y * BM, bn = blockIdx.x * BN;
    bool transB = (flags & 1) != 0;

    float acc[TM][TN];
#pragma unroll
    for (int i = 0; i < TM; i++)
#pragma unroll
        for (int j = 0; j < TN; j++) acc[i][j] = 0.f;

    for (int k0 = 0; k0 < K; k0 += BK) {
        // load A tile (BM x BK) transposed into As[k][m]
#pragma unroll
        for (int it = 0; it < 2; it++) {
            int flat = tid + it * 256;
            int row = flat >> 2;
            int c4 = (flat & 3) * 4;
            float4 v = *(const float4*)&A[(long long)(bm + row) * lda + k0 + c4];
            As[c4 + 0][row] = v.x;
            As[c4 + 1][row] = v.y;
            As[c4 + 2][row] = v.z;
            As[c4 + 3][row] = v.w;
        }
        if (transB) {
#pragma unroll
            for (int it = 0; it < 2; it++) {
                int flat = tid + it * 256;
                int row = flat >> 2;
                int c4 = (flat & 3) * 4;
                float4 v = *(const float4*)&B[(long long)(bn + row) * ldb + k0 + c4];
                Bs[c4 + 0][row] = v.x;
                Bs[c4 + 1][row] = v.y;
                Bs[c4 + 2][row] = v.z;
                Bs[c4 + 3][row] = v.w;
            }
        } else {
#pragma unroll
            for (int it = 0; it < 2; it++) {
                int flat = tid + it * 256;
                int kk = flat >> 5;
                int n4 = (flat & 31) * 4;
                float4 v = *(const float4*)&B[(long long)(k0 + kk) * ldb + bn + n4];
                *(float4*)&Bs[kk][n4] = v;
            }
        }
        __syncthreads();

#pragma unroll
        for (int kk = 0; kk < BK; kk++) {
            float ra[TM], rb[TN];
#pragma unroll
            for (int i = 0; i < TM; i += 4) *(float4*)&ra[i] = *(const float4*)&As[kk][ty * TM + i];
#pragma unroll
            for (int j = 0; j < TN; j += 4) *(float4*)&rb[j] = *(const float4*)&Bs[kk][tx * TN + j];
#pragma unroll
            for (int i = 0; i < TM; i++)
#pragma unroll
                for (int j = 0; j < TN; j++) acc[i][j] += ra[i] * rb[j];
        }
        __syncthreads();
    }

    bool relu = (flags & 2) != 0;
#pragma unroll
    for (int i = 0; i < TM; i++) {
        int r = bm + ty * TM + i;
#pragma unroll
        for (int j = 0; j < TN; j += 4) {
            int c = bn + tx * TN + j;
            float4 o;
            float* po = &o.x;
#pragma unroll
            for (int q = 0; q < 4; q++) {
                float v = alpha * acc[i][j + q];
                if (bias) v += bias[c + q];
                if (relu) v = fmaxf(v, 0.f);
                po[q] = v;
            }
            *(float4*)&C[(long long)r * ldc + c] = o;
        }
    }
}

// ---------------- row softmax over 512 columns (warp per row) ----------------
__global__ __launch_bounds__(256) void softmax_rows(float* __restrict__ s)
{
    int row = blockIdx.x * 8 + (threadIdx.x >> 5);
    int lane = threadIdx.x & 31;
    float* p = s + (long long)row * 512;

    float v[16];
    float m = -1e30f;
#pragma unroll
    for (int i = 0; i < 16; i++) {
        v[i] = p[lane + 32 * i];
        m = fmaxf(m, v[i]);
    }
#pragma unroll
    for (int off = 16; off; off >>= 1) m = fmaxf(m, __shfl_xor_sync(0xffffffffu, m, off));
    float sum = 0.f;
#pragma unroll
    for (int i = 0; i < 16; i++) {
        v[i] = expf(v[i] - m);   // accurate exp: Viterbi-upstream
        sum += v[i];
    }
#pragma unroll
    for (int off = 16; off; off >>= 1) sum += __shfl_xor_sync(0xffffffffu, sum, off);
    float inv = 1.f / sum;
#pragma unroll
    for (int i = 0; i < 16; i++) p[lane + 32 * i] = v[i] * inv;
}

// ---------------- emissions (24 CRF logits) + 2-class log-softmax head --------
__global__ __launch_bounds__(256) void emissions_kernel(
    const float* __restrict__ dec,
    const float* __restrict__ crf_w, const float* __restrict__ crf_b,
    const float* __restrict__ ent_w, const float* __restrict__ ent_b,
    float* __restrict__ em, float* __restrict__ seg_out)
{
    int row = blockIdx.x * 8 + (threadIdx.x >> 5);
    int lane = threadIdx.x & 31;
    const float* a = dec + (long long)row * 512;

    float acc[26];
#pragma unroll
    for (int o = 0; o < 26; o++) acc[o] = 0.f;

    for (int kk = lane; kk < 512; kk += 32) {
        float av = a[kk];
#pragma unroll
        for (int o = 0; o < 24; o++) acc[o] += av * crf_w[o * 512 + kk];
        acc[24] += av * ent_w[kk];
        acc[25] += av * ent_w[512 + kk];
    }
#pragma unroll
    for (int o = 0; o < 26; o++) {
#pragma unroll
        for (int off = 16; off; off >>= 1) acc[o] += __shfl_down_sync(0xffffffffu, acc[o], off);
    }
    if (lane == 0) {
#pragma unroll
        for (int o = 0; o < 24; o++) em[(long long)row * 24 + o] = acc[o] + crf_b[o];
        float z0 = acc[24] + ent_b[0];
        float z1 = acc[25] + ent_b[1];
        float m = fmaxf(z0, z1);
        float l = m + logf(expf(z0 - m) + expf(z1 - m));
        seg_out[(long long)row * 2 + 0] = z0 - l;
        seg_out[(long long)row * 2 + 1] = z1 - l;
    }
}

// ---------------- CRF: numerator + forward (logsumexp) + Viterbi --------------
// One block per batch. Warp0 lanes 0..23: logsumexp scan. Warp1 lanes 0..23: Viterbi.
__global__ __launch_bounds__(64) void crf_kernel(
    const float* __restrict__ em, const int* __restrict__ labels,
    const float* __restrict__ start_t, const float* __restrict__ end_t,
    const float* __restrict__ trans,
    float* __restrict__ out_crf, float* __restrict__ llh_part)
{
    __shared__ float tr[24 * 24];
    __shared__ float lse[24], vit[24];
    __shared__ unsigned char hist[511 * 24];
    __shared__ float red[64];
    __shared__ float s_num;

    int b = blockIdx.x, tid = threadIdx.x;
    const float* e0 = em + (long long)b * 512 * 24;
    const int* lab = labels + b * 512;

    for (int i = tid; i < 576; i += 64) tr[i] = trans[i];
    __syncthreads();

    // numerator partial sums over t = 1..511 (mask is all ones by construction)
    float local = 0.f;
    for (int t = 1 + tid; t < 512; t += 64) {
        int lp = lab[t - 1], lc = lab[t];
        local += tr[lp * 24 + lc] + e0[t * 24 + lc];
    }
    red[tid] = local;
    if (tid < 24) { float v = start_t[tid] + e0[tid]; lse[tid] = v; vit[tid] = v; }
    __syncthreads();
    if (tid == 0) {
        float s = 0.f;
        for (int i = 0; i < 64; i++) s += red[i];
        int l0 = lab[0], lN = lab[511];
        s_num = s + start_t[l0] + e0[l0] + end_t[lN];
    }
    __syncthreads();

    for (int t = 1; t < 512; t++) {
        const float* e = e0 + t * 24;
        float nl = 0.f, nv = 0.f;
        int bi = 0;
        if (tid < 24) {
            int j = tid;
            float m = -1e30f;
#pragma unroll
            for (int i = 0; i < 24; i++) m = fmaxf(m, lse[i] + tr[i * 24 + j]);
            float s = 0.f;
#pragma unroll
            for (int i = 0; i < 24; i++) s += __expf(lse[i] + tr[i * 24 + j] - m);
            nl = m + __logf(s) + e[j];
        } else if (tid >= 32 && tid < 56) {
            int j = tid - 32;
            float bm = -1e30f;
#pragma unroll
            for (int i = 0; i < 24; i++) {
                float v = vit[i] + tr[i * 24 + j];
                if (v > bm) { bm = v; bi = i; }   // strict > : first-max like jnp.argmax
            }
            nv = bm + e[j];
        }
        __syncthreads();
        if (tid < 24) lse[tid] = nl;
        else if (tid >= 32 && tid < 56) {
            vit[tid - 32] = nv;
            hist[(t - 1) * 24 + (tid - 32)] = (unsigned char)bi;
        }
        __syncthreads();
    }

    if (tid == 0) {
        float m = -1e30f;
        for (int j = 0; j < 24; j++) m = fmaxf(m, lse[j] + end_t[j]);
        float s = 0.f;
        for (int j = 0; j < 24; j++) s += __expf(lse[j] + end_t[j] - m);
        float den = m + __logf(s);
        llh_part[b] = s_num - den;
    }
    if (tid == 32) {
        float bm = -1e30f;
        int last = 0;
        for (int j = 0; j < 24; j++) {
            float v = vit[j] + end_t[j];
            if (v > bm) { bm = v; last = j; }
        }
        out_crf[b * 512 + 511] = (float)last;
        int tag = last;
        for (int t = 510; t >= 0; t--) {
            tag = hist[t * 24 + tag];
            out_crf[b * 512 + t] = (float)tag;
        }
    }
}

__global__ void finalize_kernel(const float* __restrict__ llh_part, float* __restrict__ out_scalar)
{
    if (threadIdx.x == 0) {
        float s = 0.f;
        for (int i = 0; i < 32; i++) s += llh_part[i];
        *out_scalar = -s / 16384.0f;
    }
}

// --------------------------------- launch -------------------------------------
extern "C" void kernel_launch(void* const* d_in, const int* in_sizes, int n_in,
                              void* d_out, int out_size)
{
    const float* enc     = (const float*)d_in[0];   // (32,512,512)
    const int*   labels  = (const int*)d_in[1];     // (32,512)
    // d_in[2] = mask (all ones by construction) — unused
    const float* Win     = (const float*)d_in[3];   // (1536,512)
    const float* bin_    = (const float*)d_in[4];   // (1536,)
    const float* Wout    = (const float*)d_in[5];   // (512,512)
    const float* bout    = (const float*)d_in[6];   // (512,)
    const float* crf_w   = (const float*)d_in[7];   // (24,512)
    const float* crf_b   = (const float*)d_in[8];   // (24,)
    const float* start_t = (const float*)d_in[9];   // (24,)
    const float* end_t   = (const float*)d_in[10];  // (24,)
    const float* trans   = (const float*)d_in[11];  // (24,24)
    const float* ent_w   = (const float*)d_in[12];  // (2,512)
    const float* ent_b   = (const float*)d_in[13];  // (2,)

    float* out = (float*)d_out;  // [crf_out 16384 | seg_out 32768 | -llh 1]

    float *qkv, *scores, *attn, *dec, *em, *llh;
    cudaGetSymbolAddress((void**)&qkv, g_qkv);
    cudaGetSymbolAddress((void**)&scores, g_scores);
    cudaGetSymbolAddress((void**)&attn, g_attn);
    cudaGetSymbolAddress((void**)&dec, g_dec);
    cudaGetSymbolAddress((void**)&em, g_em);
    cudaGetSymbolAddress((void**)&llh, g_llh);

    // 1) QKV = enc @ Win^T + bin : (16384 x 1536), K=512
    sgemm_kernel<<<dim3(1536 / BN, 16384 / BM, 1), 256>>>(
        enc, 512, 0, 0,
        Win, 512, 0, 0,
        qkv, 1536, 0, 0,
        bin_, 16384, 1536, 512, 1.0f, /*transB*/1, 1);

    // 2) scores[b,h] = Q @ K^T / 16 : 64 batched (512 x 512), K=256
    sgemm_kernel<<<dim3(512 / BN, 512 / BM, 64), 256>>>(
        qkv,        1536, 512LL * 1536, 256,
        qkv + 512,  1536, 512LL * 1536, 256,
        scores,     512,  524288LL,     262144LL,
        nullptr, 512, 512, 256, 0.0625f, /*transB*/1, 2);

    // 3) softmax over rows
    softmax_rows<<<4096, 256>>>(scores);

    // 4) attn_out[b,h] = P @ V : 64 batched (512 x 256), K=512
    sgemm_kernel<<<dim3(256 / BN, 512 / BM, 64), 256>>>(
        scores,      512,  524288LL,     262144LL,
        qkv + 1024,  1536, 512LL * 1536, 256,
        attn,        512,  262144LL,     256LL,
        nullptr, 512, 256, 512, 1.0f, /*transB*/0, 2);

    // 5) dec = relu(attn @ Wout^T + bout) : (16384 x 512), K=512
    sgemm_kernel<<<dim3(512 / BN, 16384 / BM, 1), 256>>>(
        attn, 512, 0, 0,
        Wout, 512, 0, 0,
        dec,  512, 0, 0,
        bout, 16384, 512, 512, 1.0f, /*transB|relu*/3, 1);

    // 6) emissions (24) + seg log-softmax (2); seg written straight into d_out
    emissions_kernel<<<2048, 256>>>(dec, crf_w, crf_b, ent_w, ent_b, em, out + 16384);

    // 7) CRF scan: numerator + normalizer + Viterbi (+ backtrack into d_out)
    crf_kernel<<<32, 64>>>(em, labels, start_t, end_t, trans, out, llh);

    // 8) scalar -llh
    finalize_kernel<<<1, 32>>>(llh, out + 16384 + 32768);
}